// round 15
// baseline (speedup 1.0000x reference)
#include <cuda_runtime.h>
#include <cstdint>

// Focal CTC loss — bidirectional split scan, 4 steps/barrier:
//  * R13's single-ring-warp raw cp.async ring (DEPTH 16).
//  * R14's linear cross-interval state: pair = (vU,vV,exp) float4; neighbor
//    reconcile via ex2(e_i - e_max) power-of-2 scales; renorm by exponent
//    extraction (validated: rel_err 9e-8).
//  * NEW: compute threads self-stage emissions one interval ahead — thread j
//    converts ONLY its own channel for rows t+4..t+7 into exch[slot][4+j]
//    (ring warp lanes 0-3 convert the blank), so the interval's 14 emission
//    reads are conflict-free stride-1 LDS with zero redundant ex2.
// grid = 2B (dir = bid&1, b = bid>>1), block = 160 (warps 0-3 compute, 4 ring).
// Second finisher per sample combines ll = LSE_s(alpha_Tm + beta_Tm) + focal
// weights; final scalar factorizes: mean(outer(w,loss)) = mean(loss)*mean(w).

#define CFIX  256
#define DEPTH 16
#define NEG2  (-1e30f)
#define DEADE (-1e9f)
#define LOG2E 1.4426950408889634f
#define LN2   0.6931471805599453f

__device__ float    g_mid[64][2][128][2];
__device__ float    g_tps[64][2][128];
__device__ unsigned g_done[64];
__device__ float    g_loss[64];
__device__ float    g_wsum[64];
__device__ unsigned g_ctr = 0;

__device__ __forceinline__ float ex2f(float x){ float y; asm("ex2.approx.ftz.f32 %0,%1;":"=f"(y):"f"(x)); return y; }
__device__ __forceinline__ float lg2f(float x){ float y; asm("lg2.approx.ftz.f32 %0,%1;":"=f"(y):"f"(x)); return y; }

__device__ __forceinline__ float lse2p(float a, float b, float e) {
    float hi = fmaxf(a, b), lo = fminf(a, b);
    return fmaf(e, LOG2E, hi + lg2f(1.0f + ex2f(lo - hi)));
}
__device__ __forceinline__ float lse3p(float a, float b, float c, float e) {
    float hi = fmaxf(a, b), lo = fminf(a, b);
    float m  = fmaxf(hi, c), o1 = fminf(hi, c);
    return fmaf(e, LOG2E, m + lg2f(1.0f + ex2f(o1 - m) + ex2f(lo - m)));
}
__device__ __forceinline__ float lse2(float a, float b) {
    float hi = fmaxf(a, b), lo = fminf(a, b);
    return hi + lg2f(1.0f + ex2f(lo - hi));
}
__device__ __forceinline__ float lse3(float a, float b, float c) {
    float hi = fmaxf(a, b), lo = fminf(a, b);
    float m  = fmaxf(hi, c), o1 = fminf(hi, c);
    return m + lg2f(1.0f + ex2f(o1 - m) + ex2f(lo - m));
}
__device__ __forceinline__ float toLog(float v, float e) {
    return (v > 0.0f) ? (lg2f(v) + e) : NEG2;
}

__device__ __forceinline__ void finalize(float* out, int B, int L)
{
    __threadfence();
    unsigned v = atomicAdd(&g_ctr, 1u);
    if (v == (unsigned)(B - 1)) {
        g_ctr = 0;
        __threadfence();
        float ls = 0.0f, ws = 0.0f;
        for (int i = 0; i < B; i++) {
            ls += __ldcg(&g_loss[i]);
            ws += __ldcg(&g_wsum[i]);
        }
        out[0] = (ls / (float)B) * (ws / ((float)B * (float)L));
    }
}

__global__ __launch_bounds__(160, 1)
void focal_ctc_kernel(const float* __restrict__ lp,      // (T,B,C)
                      const int*   __restrict__ targets, // (B*L)
                      const int*   __restrict__ in_len,  // (B)
                      const int*   __restrict__ tg_len,  // (B)
                      float*       __restrict__ out,
                      int T, int B, int L)
{
    __shared__ __align__(16) float  ring[DEPTH][CFIX];   // raw rows (16 KB)
    __shared__ float  exch[8][136];   // converted own-channel emissions
    __shared__ float  exchBl[8];      // converted blank per step slot
    __shared__ __align__(16) float4 ab4[2][132];   // pair state (vU,vV,e,_)
    __shared__ float  redm[4], reds[4], redww[4];
    __shared__ unsigned sflag;

    const int tid = threadIdx.x, w = tid >> 5, lane = tid & 31;
    const int bid = blockIdx.x;
    const int dir = bid & 1, b = bid >> 1;
    const int len = in_len[b], tl = tg_len[b];
    const int bL  = b * L;
    const int Tm  = len >> 1;
    const int nB  = len - 1 - Tm;
    const size_t tstr = (size_t)B * CFIX;
    const float* rowb = lp + (size_t)b * CFIX;

    uint32_t ringA = (uint32_t)__cvta_generic_to_shared(&ring[0][0]);
    #define ISSUE(SLOT, ROW)                                                        \
    {                                                                               \
        const float* s0_ = rowb + (size_t)(ROW) * tstr + lane * 4;                  \
        uint32_t d0_ = ringA + (uint32_t)(SLOT) * (CFIX * 4) + lane * 16;           \
        asm volatile("cp.async.ca.shared.global [%0], [%1], 16;" :: "r"(d0_),       "l"(s0_) : "memory"); \
        asm volatile("cp.async.ca.shared.global [%0], [%1], 16;" :: "r"(d0_ + 512), "l"(s0_ + 128) : "memory"); \
    }

    // pads: ab4 (both layouts) dead; exch pads 0..3 / 132..135 = 0 (all slots)
    if (tid < 4) { ab4[0][tid] = make_float4(0,0,DEADE,0); ab4[1][tid] = make_float4(0,0,DEADE,0); }
    if (tid >= 128 && tid < 132) { ab4[0][tid] = make_float4(0,0,DEADE,0); ab4[1][tid] = make_float4(0,0,DEADE,0); }
    if (tid < 64) { int sl = tid >> 3, p = tid & 7; exch[sl][p < 4 ? p : 128 + p] = 0.0f; }

    const int j = tid;                 // pair index (compute warps)
    const bool cw = (w < 4);
    const bool hasU = cw && (j <= L);
    const bool hasV = cw && (j <= L - 1);

    float vU = 0.f, vV = 0.f, eS = DEADE, acc = 0.0f;

    if (dir == 0) {
        // ======================= FORWARD =======================
        int c0 = 0, c1 = 0, c2 = 0, c3 = 0, c4f = 0;
        float af0 = 0.f, af1 = 0.f, af2 = 0.f, af3 = 0.f;
        if (cw) {
            if (j     < L) c0  = targets[bL + j];
            if (j >= 1 && j - 1 < L) c1 = targets[bL + j - 1];
            if (j >= 2 && j - 2 < L) c2 = targets[bL + j - 2];
            if (j >= 3 && j - 3 < L) c3 = targets[bL + j - 3];
            if (j >= 4 && j - 4 < L) c4f = targets[bL + j - 4];
            af0 = (j >= 1 && j     < L && c0 != c1)  ? 1.f : 0.f;
            af1 = (j >= 2 && j - 1 < L && c1 != c2)  ? 1.f : 0.f;
            af2 = (j >= 3 && j - 2 < L && c2 != c3)  ? 1.f : 0.f;
            af3 = (j >= 4 && j - 3 < L && c3 != c4f) ? 1.f : 0.f;
        }
        const int nI = (Tm >= 4) ? ((Tm - 4) >> 2) + 1 : 0;   // intervals: t = 1+4i, t+3 <= Tm

        // ---- prologue: rows 0..15 committed, rows 0..8 complete; blanks 1..4 ----
        if (w == 4) {
            #pragma unroll
            for (int q = 0; q < 16; q++) {
                if (q <= Tm) ISSUE(q & 15, q)
                asm volatile("cp.async.commit_group;" ::: "memory");
            }
            asm volatile("cp.async.wait_group 7;" ::: "memory");
            if (lane >= 1 && lane <= 4 && lane <= Tm)
                exchBl[lane & 7] = ex2f(ring[lane & 15][0] * LOG2E);
        }
        __syncthreads();

        // ---- t = 0 init + prime exch rows 1..4 ----
        if (cw) {
            float lc = ring[0][c0];
            acc = ex2f(lc * LOG2E);
            if (j == 0) {
                float xU = ring[0][0] * LOG2E;
                float xV = lc * LOG2E;
                eS = floorf(fmaxf(xU, xV));
                vU = ex2f(xU - eS);
                vV = ex2f(xV - eS);
            }
            ab4[0][4 + j] = make_float4(vU, vV, eS, 0);
            #pragma unroll
            for (int q = 1; q <= 4; q++)
                if (q <= Tm) exch[q & 7][4 + j] = ex2f(ring[q & 15][c0] * LOG2E);
        }

        int rb = 0;
        for (int i = 0; i < nI; i++) {
            __syncthreads();
            const int t = 1 + 4 * i;
            if (w == 4) {
                #pragma unroll
                for (int q = 0; q < 4; q++) {
                    int r = t + 15 + q;
                    if (r <= Tm) ISSUE(r & 15, r)
                    asm volatile("cp.async.commit_group;" ::: "memory");
                }
                asm volatile("cp.async.wait_group 7;" ::: "memory");
                { int r = t + 4 + lane;
                  if (lane < 4 && r <= Tm) exchBl[r & 7] = ex2f(ring[r & 15][0] * LOG2E); }
            } else {
                // stage emissions for NEXT interval (own channel only)
                #pragma unroll
                for (int q = 0; q < 4; q++) {
                    int r = t + 4 + q;
                    if (r <= Tm) exch[r & 7][4 + j] = ex2f(ring[r & 15][c0] * LOG2E);
                }
                float4 n1 = ab4[rb][3 + j], n2 = ab4[rb][2 + j];
                float4 n3 = ab4[rb][1 + j], n4 = ab4[rb][j];
                float me = fmaxf(fmaxf(eS, n1.z), fmaxf(fmaxf(n2.z, n3.z), n4.z));
                float s0 = ex2f(eS - me),  s1 = ex2f(n1.z - me);
                float s2 = ex2f(n2.z - me), s3 = ex2f(n3.z - me), s4 = ex2f(n4.z - me);
                float U0 = vU * s0,   V0 = vV * s0;
                float U1 = n1.x * s1, V1 = n1.y * s1;
                float U2 = n2.x * s2, V2 = n2.y * s2;
                float U3 = n3.x * s3, V3 = n3.y * s3;
                float V4 = n4.y * s4;
                const float* E0 = &exch[(t    ) & 7][0];
                const float* E1 = &exch[(t + 1) & 7][0];
                const float* E2 = &exch[(t + 2) & 7][0];
                const float* E3 = &exch[(t + 3) & 7][0];
                float pB0 = exchBl[(t    ) & 7], pB1 = exchBl[(t + 1) & 7];
                float pB2 = exchBl[(t + 2) & 7], pB3 = exchBl[(t + 3) & 7];
                float pA00 = E0[4 + j], pA01 = E0[3 + j], pA02 = E0[2 + j], pA03 = E0[1 + j];
                float pA10 = E1[4 + j], pA11 = E1[3 + j], pA12 = E1[2 + j];
                float pA20 = E2[4 + j], pA21 = E2[3 + j];
                float pA30 = E3[4 + j];
                acc += pA00 + pA10 + pA20 + pA30;
                float tU0 = (U0 + V1) * pB0, tV0 = fmaf(af0, V1, V0 + U0) * pA00;
                float tU1 = (U1 + V2) * pB0, tV1 = fmaf(af1, V2, V1 + U1) * pA01;
                float tU2 = (U2 + V3) * pB0, tV2 = fmaf(af2, V3, V2 + U2) * pA02;
                float tU3 = (U3 + V4) * pB0, tV3 = fmaf(af3, V4, V3 + U3) * pA03;
                float sU0 = (tU0 + tV1) * pB1, sV0 = fmaf(af0, tV1, tV0 + tU0) * pA10;
                float sU1 = (tU1 + tV2) * pB1, sV1 = fmaf(af1, tV2, tV1 + tU1) * pA11;
                float sU2 = (tU2 + tV3) * pB1, sV2 = fmaf(af2, tV3, tV2 + tU2) * pA12;
                float rU0 = (sU0 + sV1) * pB2, rV0 = fmaf(af0, sV1, sV0 + sU0) * pA20;
                float rU1 = (sU1 + sV2) * pB2, rV1 = fmaf(af1, sV2, sV1 + sU1) * pA21;
                float qU = (rU0 + rV1) * pB3,  qV = fmaf(af0, rV1, rV0 + rU0) * pA30;
                qU = hasU ? qU : 0.f;
                qV = hasV ? qV : 0.f;
                float mm = fmaxf(qU, qV);
                if (mm > 0.f) {
                    int ex = (int)(__float_as_uint(mm) >> 23) - 127;
                    float scl = __uint_as_float((unsigned)(127 - ex) << 23);
                    vU = qU * scl; vV = qV * scl; eS = me + (float)ex;
                } else { vU = 0.f; vV = 0.f; eS = DEADE; }
                ab4[rb ^ 1][4 + j] = make_float4(vU, vV, eS, 0);
            }
            rb ^= 1;
        }
        // ---- tail (<=3 single steps, log domain, direct global) ----
        const int tT = 1 + 4 * nI;
        float teB[3], teV[3];
        if (cw) {
            #pragma unroll
            for (int q = 0; q < 3; q++) {
                int t = tT + q;
                if (t <= Tm) {
                    teB[q] = __ldcg(rowb + (size_t)t * tstr);
                    teV[q] = __ldcg(rowb + (size_t)t * tstr + c0);
                }
            }
        }
        if (w == 4) { asm volatile("cp.async.wait_group 0;" ::: "memory"); }
        #pragma unroll
        for (int q = 0; q < 3; q++) {
            int t = tT + q;
            if (t <= Tm) {
                __syncthreads();
                if (cw) {
                    float4 n1 = ab4[rb][3 + j];
                    float xU = toLog(vU, eS), xV = toLog(vV, eS);
                    float xVm = toLog(n1.y, n1.z);
                    float nU = lse2p(xU, xVm, teB[q]);
                    float nV = lse3p(xV, xU, (af0 > 0.5f) ? xVm : NEG2, teV[q]);
                    acc += ex2f(teV[q] * LOG2E);
                    nU = hasU ? nU : NEG2;
                    nV = hasV ? nV : NEG2;
                    float mx = fmaxf(nU, nV);
                    if (mx > -1e29f) {
                        float eI = floorf(mx);
                        vU = ex2f(nU - eI); vV = ex2f(nV - eI); eS = eI;
                    } else { vU = 0.f; vV = 0.f; eS = DEADE; }
                    ab4[rb ^ 1][4 + j] = make_float4(vU, vV, eS, 0);
                }
                rb ^= 1;
            }
        }
    } else {
        // ======================= BACKWARD =======================
        int c0 = 0, c1 = 0, c2 = 0, c3 = 0, c4 = 0;
        float aN0 = 0.f, aN1 = 0.f, aN2 = 0.f, aN3 = 0.f;
        if (cw) {
            if (j     < L) c0 = targets[bL + j];
            if (j + 1 < L) c1 = targets[bL + j + 1];
            if (j + 2 < L) c2 = targets[bL + j + 2];
            if (j + 3 < L) c3 = targets[bL + j + 3];
            if (j + 4 < L) c4 = targets[bL + j + 4];
            aN0 = (j + 1 < L && c1 != c0) ? 1.f : 0.f;
            aN1 = (j + 2 < L && c2 != c1) ? 1.f : 0.f;
            aN2 = (j + 3 < L && c3 != c2) ? 1.f : 0.f;
            aN3 = (j + 4 < L && c4 != c3) ? 1.f : 0.f;
        }
        const int nI = (nB >= 4) ? ((nB - 4) >> 2) + 1 : 0;   // intervals: k = 4i, k+3 <= nB-1

        if (w == 4) {
            #pragma unroll
            for (int q = 0; q < 16; q++) {
                if (q < nB) ISSUE(q & 15, len - 1 - q)
                asm volatile("cp.async.commit_group;" ::: "memory");
            }
            asm volatile("cp.async.wait_group 7;" ::: "memory");
            if (lane < 4 && lane < nB)
                exchBl[lane & 7] = ex2f(ring[lane & 15][0] * LOG2E);
        }
        __syncthreads();

        if (cw) {
            vU = (j == tl)     ? 1.f : 0.f;
            vV = (j == tl - 1) ? 1.f : 0.f;
            eS = (vU > 0.f || vV > 0.f) ? 0.f : DEADE;
            ab4[0][j] = make_float4(vU, vV, eS, 0);
            #pragma unroll
            for (int q = 0; q < 4; q++)
                if (q < nB) exch[q & 7][4 + j] = ex2f(ring[q & 15][c0] * LOG2E);
        }

        int rb = 0;
        for (int i = 0; i < nI; i++) {
            __syncthreads();
            const int k = 4 * i;
            if (w == 4) {
                #pragma unroll
                for (int q = 0; q < 4; q++) {
                    int kk = k + 15 + q;
                    if (kk < nB) ISSUE(kk & 15, len - 1 - kk)
                    asm volatile("cp.async.commit_group;" ::: "memory");
                }
                asm volatile("cp.async.wait_group 7;" ::: "memory");
                { int kk = k + 4 + lane;
                  if (lane < 4 && kk < nB) exchBl[kk & 7] = ex2f(ring[kk & 15][0] * LOG2E); }
            } else {
                #pragma unroll
                for (int q = 0; q < 4; q++) {
                    int kk = k + 4 + q;
                    if (kk < nB) exch[kk & 7][4 + j] = ex2f(ring[kk & 15][c0] * LOG2E);
                }
                float4 n1 = ab4[rb][j + 1], n2 = ab4[rb][j + 2];
                float4 n3 = ab4[rb][j + 3], n4 = ab4[rb][j + 4];
                float me = fmaxf(fmaxf(eS, n1.z), fmaxf(fmaxf(n2.z, n3.z), n4.z));
                float s0 = ex2f(eS - me),  s1 = ex2f(n1.z - me);
                float s2 = ex2f(n2.z - me), s3 = ex2f(n3.z - me), s4 = ex2f(n4.z - me);
                float U0 = vU * s0,   V0 = vV * s0;
                float U1 = n1.x * s1, V1 = n1.y * s1;
                float U2 = n2.x * s2, V2 = n2.y * s2;
                float U3 = n3.x * s3, V3 = n3.y * s3;
                float U4 = n4.x * s4, V4 = n4.y * s4;
                const float* E0 = &exch[(k    ) & 7][0];
                const float* E1 = &exch[(k + 1) & 7][0];
                const float* E2 = &exch[(k + 2) & 7][0];
                const float* E3 = &exch[(k + 3) & 7][0];
                float pB0 = exchBl[(k    ) & 7], pB1 = exchBl[(k + 1) & 7];
                float pB2 = exchBl[(k + 2) & 7], pB3 = exchBl[(k + 3) & 7];
                float pA00 = E0[4 + j], pA01 = E0[5 + j], pA02 = E0[6 + j],
                      pA03 = E0[7 + j], pA04 = E0[8 + j];
                float pA10 = E1[4 + j], pA11 = E1[5 + j], pA12 = E1[6 + j], pA13 = E1[7 + j];
                float pA20 = E2[4 + j], pA21 = E2[5 + j], pA22 = E2[6 + j];
                float pA30 = E3[4 + j], pA31 = E3[5 + j];
                acc += pA00 + pA10 + pA20 + pA30;
                float w0 = V0 * pA00, w1 = V1 * pA01, w2 = V2 * pA02,
                      w3 = V3 * pA03, w4 = V4 * pA04;
                float tU0 = fmaf(U0, pB0, w0), tV0 = fmaf(aN0, w1, fmaf(U1, pB0, w0));
                float tU1 = fmaf(U1, pB0, w1), tV1 = fmaf(aN1, w2, fmaf(U2, pB0, w1));
                float tU2 = fmaf(U2, pB0, w2), tV2 = fmaf(aN2, w3, fmaf(U3, pB0, w2));
                float tU3 = fmaf(U3, pB0, w3), tV3 = fmaf(aN3, w4, fmaf(U4, pB0, w3));
                float x0 = tV0 * pA10, x1 = tV1 * pA11, x2 = tV2 * pA12, x3 = tV3 * pA13;
                float sU0 = fmaf(tU0, pB1, x0), sV0 = fmaf(aN0, x1, fmaf(tU1, pB1, x0));
                float sU1 = fmaf(tU1, pB1, x1), sV1 = fmaf(aN1, x2, fmaf(tU2, pB1, x1));
                float sU2 = fmaf(tU2, pB1, x2), sV2 = fmaf(aN2, x3, fmaf(tU3, pB1, x2));
                float y0 = sV0 * pA20, y1 = sV1 * pA21, y2 = sV2 * pA22;
                float rU0 = fmaf(sU0, pB2, y0), rV0 = fmaf(aN0, y1, fmaf(sU1, pB2, y0));
                float rU1 = fmaf(sU1, pB2, y1), rV1 = fmaf(aN1, y2, fmaf(sU2, pB2, y1));
                float z0 = rV0 * pA30, z1 = rV1 * pA31;
                float qU = fmaf(rU0, pB3, z0), qV = fmaf(aN0, z1, fmaf(rU1, pB3, z0));
                qU = hasU ? qU : 0.f;
                qV = hasV ? qV : 0.f;
                float mm = fmaxf(qU, qV);
                if (mm > 0.f) {
                    int ex = (int)(__float_as_uint(mm) >> 23) - 127;
                    float scl = __uint_as_float((unsigned)(127 - ex) << 23);
                    vU = qU * scl; vV = qV * scl; eS = me + (float)ex;
                } else { vU = 0.f; vV = 0.f; eS = DEADE; }
                ab4[rb ^ 1][j] = make_float4(vU, vV, eS, 0);
            }
            rb ^= 1;
        }
        // ---- tail (<=3 single steps, log domain, direct global) ----
        const int kT = 4 * nI;
        float teB[3], teA[3], teC[3];
        if (cw) {
            #pragma unroll
            for (int q = 0; q < 3; q++) {
                int k = kT + q;
                if (k <= nB - 1) {
                    const float* R = rowb + (size_t)(len - 1 - k) * tstr;
                    teB[q] = __ldcg(R); teA[q] = __ldcg(R + c0); teC[q] = __ldcg(R + c1);
                }
            }
        }
        if (w == 4) { asm volatile("cp.async.wait_group 0;" ::: "memory"); }
        #pragma unroll
        for (int q = 0; q < 3; q++) {
            int k = kT + q;
            if (k <= nB - 1) {
                __syncthreads();
                if (cw) {
                    float4 n1 = ab4[rb][j + 1];
                    float xU = toLog(vU, eS), xV = toLog(vV, eS);
                    float xU1 = toLog(n1.x, n1.z), xV1 = toLog(n1.y, n1.z);
                    float eB = teB[q] * LOG2E, eA = teA[q] * LOG2E, eC = teC[q] * LOG2E;
                    acc += ex2f(eA);
                    float nU = lse2(xU + eB, xV + eA);
                    float nV = lse3(xV + eA, xU1 + eB, (aN0 > 0.5f) ? (xV1 + eC) : NEG2);
                    nU = hasU ? nU : NEG2;
                    nV = hasV ? nV : NEG2;
                    float mx = fmaxf(nU, nV);
                    if (mx > -1e29f) {
                        float eI = floorf(mx);
                        vU = ex2f(nU - eI); vV = ex2f(nV - eI); eS = eI;
                    } else { vU = 0.f; vV = 0.f; eS = DEADE; }
                    ab4[rb ^ 1][j] = make_float4(vU, vV, eS, 0);
                }
                rb ^= 1;
            }
        }
    }

    // ---- publish mid-state (log2) + tps partials ----
    if (cw) {
        g_mid[b][dir][j][0] = toLog(vU, eS);
        g_mid[b][dir][j][1] = toLog(vV, eS);
        g_tps[b][dir][j]    = acc;
    }
    __threadfence();
    __syncthreads();
    if (tid == 0) sflag = atomicAdd(&g_done[b], 1u);
    __syncthreads();

    if (sflag == 1) {                    // second finisher: combine this sample
        float cU = NEG2, cV = NEG2, mj = NEG2;
        if (cw) {
            float a0 = __ldcg(&g_mid[b][0][j][0]), a1 = __ldcg(&g_mid[b][0][j][1]);
            float b0 = __ldcg(&g_mid[b][1][j][0]), b1 = __ldcg(&g_mid[b][1][j][1]);
            cU = a0 + b0;  cV = a1 + b1;
            mj = fmaxf(cU, cV);
            #pragma unroll
            for (int o = 16; o; o >>= 1) mj = fmaxf(mj, __shfl_xor_sync(0xFFFFFFFFu, mj, o));
            if (lane == 0) redm[w] = mj;
        }
        __syncthreads();
        float M = fmaxf(fmaxf(redm[0], redm[1]), fmaxf(redm[2], redm[3]));
        float sj = 0.0f, wgt = 0.0f;
        if (cw) {
            sj = ex2f(cU - M) + ex2f(cV - M);
            if (j < L) {
                float tps = __ldcg(&g_tps[b][0][j]) + __ldcg(&g_tps[b][1][j]);
                float om  = 1.0f - tps * (1.0f / (float)T);
                wgt = om * om;                       // GAMMA = 2
            }
            #pragma unroll
            for (int o = 16; o; o >>= 1) {
                sj  += __shfl_xor_sync(0xFFFFFFFFu, sj, o);
                wgt += __shfl_xor_sync(0xFFFFFFFFu, wgt, o);
            }
            if (lane == 0) { reds[w] = sj; redww[w] = wgt; }
        }
        __syncthreads();
        if (tid == 0) {
            float ss = reds[0] + reds[1] + reds[2] + reds[3];
            float ll = (M + lg2f(ss)) * LN2;
            g_loss[b] = (ll > -5e29f) ? -ll : 0.0f;   // zero_infinity
            g_wsum[b] = redww[0] + redww[1] + redww[2] + redww[3];
            g_done[b] = 0;                            // reset for graph replay
            finalize(out, B, L);
        }
    }
    #undef ISSUE
}

extern "C" void kernel_launch(void* const* d_in, const int* in_sizes, int n_in,
                              void* d_out, int out_size)
{
    const float* lp      = (const float*)d_in[0];
    const int*   targets = (const int*)d_in[1];
    const int*   in_len  = (const int*)d_in[2];
    const int*   tg_len  = (const int*)d_in[3];

    int B = in_sizes[2];                 // 64
    int L = in_sizes[1] / B;             // 100
    int T = in_sizes[0] / (B * CFIX);    // 1000

    focal_ctc_kernel<<<2 * B, 160>>>(lp, targets, in_len, tg_len, (float*)d_out, T, B, L);
}

// round 16
// speedup vs baseline: 1.2074x; 1.2074x over previous
#include <cuda_runtime.h>
#include <cstdint>

// Focal CTC loss — R13 skeleton (single ring warp, DEPTH-16 raw ring, 4-step
// linear pyramid with in-body emission ex2) + R14's linear cross-interval
// state: pair = (vU,vV,exp) float4 in smem; neighbor reconcile via
// ex2(e_i - e_max) power-of-2 scales; renorm by exponent extraction.
// This removes the 9x ex2 + 2x lg2 log<->linear round-trip from the
// dependent chain each interval. grid = 2B (dir = bid&1, b = bid>>1),
// block = 160 (warps 0-3 compute pair j=tid, warp 4 = cp.async ring).
// Second finisher per sample combines ll = LSE_s(alpha_Tm + beta_Tm) and
// focal weights; final scalar factorizes: mean(loss)*mean(w).

#define CFIX  256
#define DEPTH 16
#define NEG2  (-1e30f)
#define DEADE (-1e9f)
#define LOG2E 1.4426950408889634f
#define LN2   0.6931471805599453f

__device__ float    g_mid[64][2][128][2];
__device__ float    g_tps[64][2][128];
__device__ unsigned g_done[64];
__device__ float    g_loss[64];
__device__ float    g_wsum[64];
__device__ unsigned g_ctr = 0;

__device__ __forceinline__ float ex2f(float x){ float y; asm("ex2.approx.ftz.f32 %0,%1;":"=f"(y):"f"(x)); return y; }
__device__ __forceinline__ float lg2f(float x){ float y; asm("lg2.approx.ftz.f32 %0,%1;":"=f"(y):"f"(x)); return y; }

__device__ __forceinline__ float lse2p(float a, float b, float e) {
    float hi = fmaxf(a, b), lo = fminf(a, b);
    return fmaf(e, LOG2E, hi + lg2f(1.0f + ex2f(lo - hi)));
}
__device__ __forceinline__ float lse3p(float a, float b, float c, float e) {
    float hi = fmaxf(a, b), lo = fminf(a, b);
    float m  = fmaxf(hi, c), o1 = fminf(hi, c);
    return fmaf(e, LOG2E, m + lg2f(1.0f + ex2f(o1 - m) + ex2f(lo - m)));
}
__device__ __forceinline__ float lse2(float a, float b) {
    float hi = fmaxf(a, b), lo = fminf(a, b);
    return hi + lg2f(1.0f + ex2f(lo - hi));
}
__device__ __forceinline__ float lse3(float a, float b, float c) {
    float hi = fmaxf(a, b), lo = fminf(a, b);
    float m  = fmaxf(hi, c), o1 = fminf(hi, c);
    return m + lg2f(1.0f + ex2f(o1 - m) + ex2f(lo - m));
}
__device__ __forceinline__ float toLog(float v, float e) {
    return (v > 0.0f) ? (lg2f(v) + e) : NEG2;
}

__device__ __forceinline__ void finalize(float* out, int B, int L)
{
    __threadfence();
    unsigned v = atomicAdd(&g_ctr, 1u);
    if (v == (unsigned)(B - 1)) {
        g_ctr = 0;
        __threadfence();
        float ls = 0.0f, ws = 0.0f;
        for (int i = 0; i < B; i++) {
            ls += __ldcg(&g_loss[i]);
            ws += __ldcg(&g_wsum[i]);
        }
        out[0] = (ls / (float)B) * (ws / ((float)B * (float)L));
    }
}

__global__ __launch_bounds__(160, 1)
void focal_ctc_kernel(const float* __restrict__ lp,      // (T,B,C)
                      const int*   __restrict__ targets, // (B*L)
                      const int*   __restrict__ in_len,  // (B)
                      const int*   __restrict__ tg_len,  // (B)
                      float*       __restrict__ out,
                      int T, int B, int L)
{
    __shared__ __align__(16) float  ring[DEPTH][CFIX];  // raw rows (16 KB)
    __shared__ __align__(16) float4 ab4[2][132];        // pair state (vU,vV,e,_)
    __shared__ float redm[4], reds[4], redww[4];
    __shared__ unsigned sflag;

    const int tid = threadIdx.x, w = tid >> 5, lane = tid & 31;
    const int bid = blockIdx.x;
    const int dir = bid & 1, b = bid >> 1;
    const int len = in_len[b], tl = tg_len[b];
    const int bL  = b * L;
    const int Tm  = len >> 1;
    const int nB  = len - 1 - Tm;
    const size_t tstr = (size_t)B * CFIX;
    const float* rowb = lp + (size_t)b * CFIX;

    uint32_t ringA = (uint32_t)__cvta_generic_to_shared(&ring[0][0]);
    #define ISSUE(SLOT, ROW)                                                        \
    {                                                                               \
        const float* s0_ = rowb + (size_t)(ROW) * tstr + lane * 4;                  \
        uint32_t d0_ = ringA + (uint32_t)(SLOT) * (CFIX * 4) + lane * 16;           \
        asm volatile("cp.async.ca.shared.global [%0], [%1], 16;" :: "r"(d0_),       "l"(s0_) : "memory"); \
        asm volatile("cp.async.ca.shared.global [%0], [%1], 16;" :: "r"(d0_ + 512), "l"(s0_ + 128) : "memory"); \
    }

    // pads (both layouts): dead pairs
    if (tid < 4) { ab4[0][tid] = make_float4(0,0,DEADE,0); ab4[1][tid] = make_float4(0,0,DEADE,0); }
    if (tid >= 128 && tid < 132) { ab4[0][tid] = make_float4(0,0,DEADE,0); ab4[1][tid] = make_float4(0,0,DEADE,0); }

    const int j = tid;                 // pair index (compute warps)
    const bool cw = (w < 4);
    const bool hasU = cw && (j <= L);
    const bool hasV = cw && (j <= L - 1);

    float vU = 0.f, vV = 0.f, eS = DEADE, acc = 0.0f;

    if (dir == 0) {
        // ======================= FORWARD =======================
        int c0 = 0, c1 = 0, c2 = 0, c3 = 0, c4f = 0;
        float af0 = 0.f, af1 = 0.f, af2 = 0.f, af3 = 0.f;
        if (cw) {
            if (j     < L) c0  = targets[bL + j];
            if (j >= 1 && j - 1 < L) c1 = targets[bL + j - 1];
            if (j >= 2 && j - 2 < L) c2 = targets[bL + j - 2];
            if (j >= 3 && j - 3 < L) c3 = targets[bL + j - 3];
            if (j >= 4 && j - 4 < L) c4f = targets[bL + j - 4];
            af0 = (j >= 1 && j     < L && c0 != c1)  ? 1.f : 0.f;
            af1 = (j >= 2 && j - 1 < L && c1 != c2)  ? 1.f : 0.f;
            af2 = (j >= 3 && j - 2 < L && c2 != c3)  ? 1.f : 0.f;
            af3 = (j >= 4 && j - 3 < L && c3 != c4f) ? 1.f : 0.f;
        }
        const int nI = (Tm >= 4) ? ((Tm - 4) >> 2) + 1 : 0;   // intervals t = 1+4i, t+3 <= Tm

        if (w == 4) {                  // prologue: rows 0..12 committed, 0..4 done
            #pragma unroll
            for (int i = 0; i < 13; i++) {
                if (i <= Tm) ISSUE(i & 15, i)
                asm volatile("cp.async.commit_group;" ::: "memory");
            }
            asm volatile("cp.async.wait_group 8;" ::: "memory");
        }
        __syncthreads();

        // t = 0 init (linear, per-pair exponent)
        if (cw) {
            float lc = ring[0][c0];
            acc = ex2f(lc * LOG2E);
            if (j == 0) {
                float xU = ring[0][0] * LOG2E;
                float xV = lc * LOG2E;
                eS = floorf(fmaxf(xU, xV));
                vU = ex2f(xU - eS);
                vV = ex2f(xV - eS);
            }
            ab4[0][4 + j] = make_float4(vU, vV, eS, 0);
        }

        int rb = 0;
        for (int i = 0; i < nI; i++) {
            __syncthreads();
            const int t = 1 + 4 * i;
            if (w == 4) {
                #pragma unroll
                for (int q = 0; q < 4; q++) {
                    int r = t + 12 + q;
                    if (r <= Tm) ISSUE(r & 15, r)
                    asm volatile("cp.async.commit_group;" ::: "memory");
                }
                asm volatile("cp.async.wait_group 8;" ::: "memory");
            } else {
                float4 n1 = ab4[rb][3 + j], n2 = ab4[rb][2 + j];
                float4 n3 = ab4[rb][1 + j], n4 = ab4[rb][j];
                // exponent reconcile (off-chain scale factors)
                float me = fmaxf(fmaxf(eS, n1.z), fmaxf(fmaxf(n2.z, n3.z), n4.z));
                float s0 = ex2f(eS - me),  s1 = ex2f(n1.z - me);
                float s2 = ex2f(n2.z - me), s3 = ex2f(n3.z - me), s4 = ex2f(n4.z - me);
                float U0 = vU * s0,   V0 = vV * s0;
                float U1 = n1.x * s1, V1 = n1.y * s1;
                float U2 = n2.x * s2, V2 = n2.y * s2;
                float U3 = n3.x * s3, V3 = n3.y * s3;
                float V4 = n4.y * s4;
                // emissions: in-body ex2 straight from the raw ring (R13)
                const float* R0 = &ring[(t    ) & 15][0];
                const float* R1 = &ring[(t + 1) & 15][0];
                const float* R2 = &ring[(t + 2) & 15][0];
                const float* R3 = &ring[(t + 3) & 15][0];
                float pB0 = ex2f(R0[0] * LOG2E), pB1 = ex2f(R1[0] * LOG2E);
                float pB2 = ex2f(R2[0] * LOG2E), pB3 = ex2f(R3[0] * LOG2E);
                float pA00 = ex2f(R0[c0] * LOG2E), pA01 = ex2f(R0[c1] * LOG2E);
                float pA02 = ex2f(R0[c2] * LOG2E), pA03 = ex2f(R0[c3] * LOG2E);
                float pA10 = ex2f(R1[c0] * LOG2E), pA11 = ex2f(R1[c1] * LOG2E);
                float pA12 = ex2f(R1[c2] * LOG2E);
                float pA20 = ex2f(R2[c0] * LOG2E), pA21 = ex2f(R2[c1] * LOG2E);
                float pA30 = ex2f(R3[c0] * LOG2E);
                acc += pA00 + pA10 + pA20 + pA30;
                // 4-step redundant pyramid (pure FMA)
                float tU0 = (U0 + V1) * pB0, tV0 = fmaf(af0, V1, V0 + U0) * pA00;
                float tU1 = (U1 + V2) * pB0, tV1 = fmaf(af1, V2, V1 + U1) * pA01;
                float tU2 = (U2 + V3) * pB0, tV2 = fmaf(af2, V3, V2 + U2) * pA02;
                float tU3 = (U3 + V4) * pB0, tV3 = fmaf(af3, V4, V3 + U3) * pA03;
                float sU0 = (tU0 + tV1) * pB1, sV0 = fmaf(af0, tV1, tV0 + tU0) * pA10;
                float sU1 = (tU1 + tV2) * pB1, sV1 = fmaf(af1, tV2, tV1 + tU1) * pA11;
                float sU2 = (tU2 + tV3) * pB1, sV2 = fmaf(af2, tV3, tV2 + tU2) * pA12;
                float rU0 = (sU0 + sV1) * pB2, rV0 = fmaf(af0, sV1, sV0 + sU0) * pA20;
                float rU1 = (sU1 + sV2) * pB2, rV1 = fmaf(af1, sV2, sV1 + sU1) * pA21;
                float qU = (rU0 + rV1) * pB3,  qV = fmaf(af0, rV1, rV0 + rU0) * pA30;
                qU = hasU ? qU : 0.f;
                qV = hasV ? qV : 0.f;
                // renorm: exponent extraction (no lg2 on chain)
                float mm = fmaxf(qU, qV);
                if (mm > 0.f) {
                    int ex = (int)(__float_as_uint(mm) >> 23) - 127;
                    float scl = __uint_as_float((unsigned)(127 - ex) << 23);
                    vU = qU * scl; vV = qV * scl; eS = me + (float)ex;
                } else { vU = 0.f; vV = 0.f; eS = DEADE; }
                ab4[rb ^ 1][4 + j] = make_float4(vU, vV, eS, 0);
            }
            rb ^= 1;
        }
        if (w == 4) { asm volatile("cp.async.wait_group 0;" ::: "memory"); }
        // tail (<=3 single steps, log domain, from ring)
        for (int t = 1 + 4 * nI; t <= Tm; t++) {
            __syncthreads();
            if (cw) {
                float4 n1 = ab4[rb][3 + j];
                const float* R = &ring[t & 15][0];
                float eB = R[0], eV = R[c0];
                acc += ex2f(eV * LOG2E);
                float xU = toLog(vU, eS), xV = toLog(vV, eS);
                float xVm = toLog(n1.y, n1.z);
                float nU = lse2p(xU, xVm, eB);
                float nV = lse3p(xV, xU, (af0 > 0.5f) ? xVm : NEG2, eV);
                nU = hasU ? nU : NEG2;
                nV = hasV ? nV : NEG2;
                float mx = fmaxf(nU, nV);
                if (mx > -1e29f) {
                    float eI = floorf(mx);
                    vU = ex2f(nU - eI); vV = ex2f(nV - eI); eS = eI;
                } else { vU = 0.f; vV = 0.f; eS = DEADE; }
                ab4[rb ^ 1][4 + j] = make_float4(vU, vV, eS, 0);
            }
            rb ^= 1;
        }
    } else {
        // ======================= BACKWARD =======================
        int c0 = 0, c1 = 0, c2 = 0, c3 = 0, c4 = 0;
        float aN0 = 0.f, aN1 = 0.f, aN2 = 0.f, aN3 = 0.f;
        if (cw) {
            if (j     < L) c0 = targets[bL + j];
            if (j + 1 < L) c1 = targets[bL + j + 1];
            if (j + 2 < L) c2 = targets[bL + j + 2];
            if (j + 3 < L) c3 = targets[bL + j + 3];
            if (j + 4 < L) c4 = targets[bL + j + 4];
            aN0 = (j + 1 < L && c1 != c0) ? 1.f : 0.f;
            aN1 = (j + 2 < L && c2 != c1) ? 1.f : 0.f;
            aN2 = (j + 3 < L && c3 != c2) ? 1.f : 0.f;
            aN3 = (j + 4 < L && c4 != c3) ? 1.f : 0.f;
        }
        const int nI = (nB >= 4) ? ((nB - 4) >> 2) + 1 : 0;   // intervals k = 4i, k+3 <= nB-1

        if (w == 4) {
            #pragma unroll
            for (int i = 0; i < 13; i++) {
                if (i < nB) ISSUE(i & 15, len - 1 - i)
                asm volatile("cp.async.commit_group;" ::: "memory");
            }
            asm volatile("cp.async.wait_group 8;" ::: "memory");
        }
        __syncthreads();
        if (cw) {
            vU = (j == tl)     ? 1.f : 0.f;
            vV = (j == tl - 1) ? 1.f : 0.f;
            eS = (vU > 0.f || vV > 0.f) ? 0.f : DEADE;
            ab4[0][j] = make_float4(vU, vV, eS, 0);
        }

        int rb = 0;
        for (int i = 0; i < nI; i++) {
            __syncthreads();
            const int k = 4 * i;
            if (w == 4) {
                #pragma unroll
                for (int q = 0; q < 4; q++) {
                    int kk = k + 12 + q;
                    if (kk < nB) ISSUE(kk & 15, len - 1 - kk)
                    asm volatile("cp.async.commit_group;" ::: "memory");
                }
                asm volatile("cp.async.wait_group 8;" ::: "memory");
            } else {
                float4 n1 = ab4[rb][j + 1], n2 = ab4[rb][j + 2];
                float4 n3 = ab4[rb][j + 3], n4 = ab4[rb][j + 4];
                float me = fmaxf(fmaxf(eS, n1.z), fmaxf(fmaxf(n2.z, n3.z), n4.z));
                float s0 = ex2f(eS - me),  s1 = ex2f(n1.z - me);
                float s2 = ex2f(n2.z - me), s3 = ex2f(n3.z - me), s4 = ex2f(n4.z - me);
                float U0 = vU * s0,   V0 = vV * s0;
                float U1 = n1.x * s1, V1 = n1.y * s1;
                float U2 = n2.x * s2, V2 = n2.y * s2;
                float U3 = n3.x * s3, V3 = n3.y * s3;
                float U4 = n4.x * s4, V4 = n4.y * s4;
                const float* R0 = &ring[(k    ) & 15][0];
                const float* R1 = &ring[(k + 1) & 15][0];
                const float* R2 = &ring[(k + 2) & 15][0];
                const float* R3 = &ring[(k + 3) & 15][0];
                float pB0 = ex2f(R0[0] * LOG2E), pB1 = ex2f(R1[0] * LOG2E);
                float pB2 = ex2f(R2[0] * LOG2E), pB3 = ex2f(R3[0] * LOG2E);
                float pA00 = ex2f(R0[c0] * LOG2E), pA01 = ex2f(R0[c1] * LOG2E);
                float pA02 = ex2f(R0[c2] * LOG2E), pA03 = ex2f(R0[c3] * LOG2E);
                float pA04 = ex2f(R0[c4] * LOG2E);
                float pA10 = ex2f(R1[c0] * LOG2E), pA11 = ex2f(R1[c1] * LOG2E);
                float pA12 = ex2f(R1[c2] * LOG2E), pA13 = ex2f(R1[c3] * LOG2E);
                float pA20 = ex2f(R2[c0] * LOG2E), pA21 = ex2f(R2[c1] * LOG2E);
                float pA22 = ex2f(R2[c2] * LOG2E);
                float pA30 = ex2f(R3[c0] * LOG2E), pA31 = ex2f(R3[c1] * LOG2E);
                acc += pA00 + pA10 + pA20 + pA30;
                float w0 = V0 * pA00, w1 = V1 * pA01, w2 = V2 * pA02,
                      w3 = V3 * pA03, w4 = V4 * pA04;
                float tU0 = fmaf(U0, pB0, w0), tV0 = fmaf(aN0, w1, fmaf(U1, pB0, w0));
                float tU1 = fmaf(U1, pB0, w1), tV1 = fmaf(aN1, w2, fmaf(U2, pB0, w1));
                float tU2 = fmaf(U2, pB0, w2), tV2 = fmaf(aN2, w3, fmaf(U3, pB0, w2));
                float tU3 = fmaf(U3, pB0, w3), tV3 = fmaf(aN3, w4, fmaf(U4, pB0, w3));
                float x0 = tV0 * pA10, x1 = tV1 * pA11, x2 = tV2 * pA12, x3 = tV3 * pA13;
                float sU0 = fmaf(tU0, pB1, x0), sV0 = fmaf(aN0, x1, fmaf(tU1, pB1, x0));
                float sU1 = fmaf(tU1, pB1, x1), sV1 = fmaf(aN1, x2, fmaf(tU2, pB1, x1));
                float sU2 = fmaf(tU2, pB1, x2), sV2 = fmaf(aN2, x3, fmaf(tU3, pB1, x2));
                float y0 = sV0 * pA20, y1 = sV1 * pA21, y2 = sV2 * pA22;
                float rU0 = fmaf(sU0, pB2, y0), rV0 = fmaf(aN0, y1, fmaf(sU1, pB2, y0));
                float rU1 = fmaf(sU1, pB2, y1), rV1 = fmaf(aN1, y2, fmaf(sU2, pB2, y1));
                float z0 = rV0 * pA30, z1 = rV1 * pA31;
                float qU = fmaf(rU0, pB3, z0), qV = fmaf(aN0, z1, fmaf(rU1, pB3, z0));
                qU = hasU ? qU : 0.f;
                qV = hasV ? qV : 0.f;
                float mm = fmaxf(qU, qV);
                if (mm > 0.f) {
                    int ex = (int)(__float_as_uint(mm) >> 23) - 127;
                    float scl = __uint_as_float((unsigned)(127 - ex) << 23);
                    vU = qU * scl; vV = qV * scl; eS = me + (float)ex;
                } else { vU = 0.f; vV = 0.f; eS = DEADE; }
                ab4[rb ^ 1][j] = make_float4(vU, vV, eS, 0);
            }
            rb ^= 1;
        }
        if (w == 4) { asm volatile("cp.async.wait_group 0;" ::: "memory"); }
        for (int k = 4 * nI; k <= nB - 1; k++) {   // tail (log domain, from ring)
            __syncthreads();
            if (cw) {
                float4 n1 = ab4[rb][j + 1];
                const float* R = &ring[k & 15][0];
                float eB = R[0] * LOG2E, eA = R[c0] * LOG2E, eC = R[c1] * LOG2E;
                acc += ex2f(eA);
                float xU = toLog(vU, eS), xV = toLog(vV, eS);
                float xU1 = toLog(n1.x, n1.z), xV1 = toLog(n1.y, n1.z);
                float nU = lse2(xU + eB, xV + eA);
                float nV = lse3(xV + eA, xU1 + eB, (aN0 > 0.5f) ? (xV1 + eC) : NEG2);
                nU = hasU ? nU : NEG2;
                nV = hasV ? nV : NEG2;
                float mx = fmaxf(nU, nV);
                if (mx > -1e29f) {
                    float eI = floorf(mx);
                    vU = ex2f(nU - eI); vV = ex2f(nV - eI); eS = eI;
                } else { vU = 0.f; vV = 0.f; eS = DEADE; }
                ab4[rb ^ 1][j] = make_float4(vU, vV, eS, 0);
            }
            rb ^= 1;
        }
    }

    // ---- publish mid-state (log2) + tps partials ----
    if (cw) {
        g_mid[b][dir][j][0] = toLog(vU, eS);
        g_mid[b][dir][j][1] = toLog(vV, eS);
        g_tps[b][dir][j]    = acc;
    }
    __threadfence();
    __syncthreads();
    if (tid == 0) sflag = atomicAdd(&g_done[b], 1u);
    __syncthreads();

    if (sflag == 1) {                    // second finisher: combine this sample
        float cU = NEG2, cV = NEG2, mj = NEG2;
        if (cw) {
            float a0 = __ldcg(&g_mid[b][0][j][0]), a1 = __ldcg(&g_mid[b][0][j][1]);
            float b0 = __ldcg(&g_mid[b][1][j][0]), b1 = __ldcg(&g_mid[b][1][j][1]);
            cU = a0 + b0;  cV = a1 + b1;
            mj = fmaxf(cU, cV);
            #pragma unroll
            for (int o = 16; o; o >>= 1) mj = fmaxf(mj, __shfl_xor_sync(0xFFFFFFFFu, mj, o));
            if (lane == 0) redm[w] = mj;
        }
        __syncthreads();
        float M = fmaxf(fmaxf(redm[0], redm[1]), fmaxf(redm[2], redm[3]));
        float sj = 0.0f, wgt = 0.0f;
        if (cw) {
            sj = ex2f(cU - M) + ex2f(cV - M);
            if (j < L) {
                float tps = __ldcg(&g_tps[b][0][j]) + __ldcg(&g_tps[b][1][j]);
                float om  = 1.0f - tps * (1.0f / (float)T);
                wgt = om * om;                       // GAMMA = 2
            }
            #pragma unroll
            for (int o = 16; o; o >>= 1) {
                sj  += __shfl_xor_sync(0xFFFFFFFFu, sj, o);
                wgt += __shfl_xor_sync(0xFFFFFFFFu, wgt, o);
            }
            if (lane == 0) { reds[w] = sj; redww[w] = wgt; }
        }
        __syncthreads();
        if (tid == 0) {
            float ss = reds[0] + reds[1] + reds[2] + reds[3];
            float ll = (M + lg2f(ss)) * LN2;
            g_loss[b] = (ll > -5e29f) ? -ll : 0.0f;   // zero_infinity
            g_wsum[b] = redww[0] + redww[1] + redww[2] + redww[3];
            g_done[b] = 0;                            // reset for graph replay
            finalize(out, B, L);
        }
    }
    #undef ISSUE
}

extern "C" void kernel_launch(void* const* d_in, const int* in_sizes, int n_in,
                              void* d_out, int out_size)
{
    const float* lp      = (const float*)d_in[0];
    const int*   targets = (const int*)d_in[1];
    const int*   in_len  = (const int*)d_in[2];
    const int*   tg_len  = (const int*)d_in[3];

    int B = in_sizes[2];                 // 64
    int L = in_sizes[1] / B;             // 100
    int T = in_sizes[0] / (B * CFIX);    // 1000

    focal_ctc_kernel<<<2 * B, 160>>>(lp, targets, in_len, tg_len, (float*)d_out, T, B, L);
}